// round 1
// baseline (speedup 1.0000x reference)
#include <cuda_runtime.h>

#define BB 128
#define TT 2048
#define NI 128
#define NH 128

// ======================================================================
// Kernel A: igates = inputs @ W_in^T + (b_in + b_hh)   -> written to out
//   M = B*T = 262144, N = 128, K = 128.  TM = 64 rows / CTA, 256 threads.
//   smem: Ast[k][64] (transposed input tile, 32KB) + Wst[k][128] (64KB).
//   Each thread: 4x8 register micro-tile, K fully resident -> one tile load.
// ======================================================================
extern __shared__ float g_smem[];

__global__ void __launch_bounds__(256, 2) igates_kernel(
    const float* __restrict__ inp,
    const float* __restrict__ W_in,
    const float* __restrict__ b_in,
    const float* __restrict__ b_hh,
    float* __restrict__ out)
{
    float* Ast = g_smem;            // [128][64]
    float* Wst = g_smem + 128 * 64; // [128][128]
    const int tid = threadIdx.x;
    const long m0 = (long)blockIdx.x * 64;

    // Load A tile transposed: Ast[k][r] = inp[(m0+r)*NI + k]
    // f: linear float4 index; lanes walk rows (r contiguous) -> STS conflict-free
    #pragma unroll
    for (int it = 0; it < 8; it++) {
        int f  = tid + it * 256;        // 0 .. 2047
        int r  = f & 63;
        int k4 = f >> 6;                // 0 .. 31
        float4 v = *(const float4*)(inp + (m0 + r) * NI + (long)k4 * 4);
        Ast[(k4 * 4 + 0) * 64 + r] = v.x;
        Ast[(k4 * 4 + 1) * 64 + r] = v.y;
        Ast[(k4 * 4 + 2) * 64 + r] = v.z;
        Ast[(k4 * 4 + 3) * 64 + r] = v.w;
    }
    // Load W transposed: Wst[k][j] = W_in[j*NI + k]
    #pragma unroll
    for (int it = 0; it < 16; it++) {
        int f  = tid + it * 256;        // 0 .. 4095
        int j  = f & 127;
        int k4 = f >> 7;                // 0 .. 31
        float4 v = *(const float4*)(W_in + (long)j * NI + (long)k4 * 4);
        Wst[(k4 * 4 + 0) * 128 + j] = v.x;
        Wst[(k4 * 4 + 1) * 128 + j] = v.y;
        Wst[(k4 * 4 + 2) * 128 + j] = v.z;
        Wst[(k4 * 4 + 3) * 128 + j] = v.w;
    }
    __syncthreads();

    const int tx = tid & 15;   // col group: cols tx*8 .. tx*8+7
    const int ty = tid >> 4;   // row group: rows ty*4 .. ty*4+3

    float acc[4][8];
    #pragma unroll
    for (int r = 0; r < 4; r++)
        #pragma unroll
        for (int c = 0; c < 8; c++) acc[r][c] = 0.f;

    #pragma unroll 4
    for (int k = 0; k < 128; k++) {
        float4 a  = *(const float4*)(Ast + k * 64 + ty * 4);
        float4 w0 = *(const float4*)(Wst + k * 128 + tx * 8);
        float4 w1 = *(const float4*)(Wst + k * 128 + tx * 8 + 4);
        float av[4] = {a.x, a.y, a.z, a.w};
        float wv[8] = {w0.x, w0.y, w0.z, w0.w, w1.x, w1.y, w1.z, w1.w};
        #pragma unroll
        for (int r = 0; r < 4; r++)
            #pragma unroll
            for (int c = 0; c < 8; c++)
                acc[r][c] = fmaf(av[r], wv[c], acc[r][c]);
    }

    // bias = b_in + b_hh (cached in L1/L2; tiny)
    float bias[8];
    #pragma unroll
    for (int c = 0; c < 8; c++)
        bias[c] = b_in[tx * 8 + c] + b_hh[tx * 8 + c];

    #pragma unroll
    for (int r = 0; r < 4; r++) {
        long row = m0 + ty * 4 + r;
        float4 o0, o1;
        o0.x = acc[r][0] + bias[0]; o0.y = acc[r][1] + bias[1];
        o0.z = acc[r][2] + bias[2]; o0.w = acc[r][3] + bias[3];
        o1.x = acc[r][4] + bias[4]; o1.y = acc[r][5] + bias[5];
        o1.z = acc[r][6] + bias[6]; o1.w = acc[r][7] + bias[7];
        *(float4*)(out + row * NH + tx * 8)     = o0;
        *(float4*)(out + row * NH + tx * 8 + 4) = o1;
    }
}

// ======================================================================
// Kernel B: sequential recurrence, one CTA per batch row (128 CTAs x 128 thr)
//   h_new[j] = sigmoid(ig[t][j] + sum_i h[i] * W_hh[j][i])
//   - thread j holds W_hh[j][0..127] in 128 registers (loaded once)
//   - h double-buffered in smem -> one __syncthreads per step
//   - igates read in-place from out, overwritten with h (each elem RAW once)
//   - software prefetch of next step's ig hides gmem latency
// ======================================================================
__global__ void __launch_bounds__(128, 1) rnn_scan_kernel(
    const float* __restrict__ hidden0,
    const float* __restrict__ W_hh,
    float* __restrict__ io)    // [B][T][NH], contains igates on entry
{
    __shared__ float hb[2][NH];
    const int j = threadIdx.x;
    const int b = blockIdx.x;

    // W_hh row j into registers (one-time, 64KB/CTA, L2-resident after wave 1)
    float w[128];
    #pragma unroll
    for (int i = 0; i < 128; i++) w[i] = W_hh[(long)j * NH + i];

    hb[0][j] = hidden0[(long)b * NH + j];
    __syncthreads();

    float* row = io + (long)b * TT * NH + j;
    float ig = row[0];
    int cur = 0;

    for (int t = 0; t < TT; t++) {
        float ig_next = (t + 1 < TT) ? row[(long)(t + 1) * NH] : 0.f;

        float a0 = 0.f, a1 = 0.f, a2 = 0.f, a3 = 0.f;
        const float4* h4 = (const float4*)(&hb[cur][0]);
        #pragma unroll
        for (int i = 0; i < 32; i++) {
            float4 hv = h4[i];   // broadcast LDS.128, conflict-free
            a0 = fmaf(w[4 * i + 0], hv.x, a0);
            a1 = fmaf(w[4 * i + 1], hv.y, a1);
            a2 = fmaf(w[4 * i + 2], hv.z, a2);
            a3 = fmaf(w[4 * i + 3], hv.w, a3);
        }
        float pre = ig + ((a0 + a1) + (a2 + a3));
        float h = 1.0f / (1.0f + __expf(-pre));

        row[(long)t * NH] = h;     // overwrite igates slot with output h
        hb[cur ^ 1][j] = h;
        __syncthreads();
        cur ^= 1;
        ig = ig_next;
    }
}

// ======================================================================
extern "C" void kernel_launch(void* const* d_in, const int* in_sizes, int n_in,
                              void* d_out, int out_size)
{
    const float* inp     = (const float*)d_in[0];  // [B,T,NI]
    const float* hidden0 = (const float*)d_in[1];  // [B,NH]
    const float* W_in    = (const float*)d_in[2];  // [NH,NI]
    const float* b_in    = (const float*)d_in[3];  // [NH]
    const float* W_hh    = (const float*)d_in[4];  // [NH,NH]
    const float* b_hh    = (const float*)d_in[5];  // [NH]
    float* out = (float*)d_out;                    // [B,T,NH]

    cudaFuncSetAttribute(igates_kernel,
                         cudaFuncAttributeMaxDynamicSharedMemorySize, 98304);

    const int n_tiles = (BB * TT) / 64;   // 4096
    igates_kernel<<<n_tiles, 256, 98304>>>(inp, W_in, b_in, b_hh, out);
    rnn_scan_kernel<<<BB, 128>>>(hidden0, W_hh, out);
}

// round 2
// speedup vs baseline: 1.0439x; 1.0439x over previous
#include <cuda_runtime.h>

#define BB 128
#define TT 2048
#define NI 128
#define NH 128

// ======================================================================
// Kernel A: igates = inputs @ W_in^T + (b_in + b_hh)   -> written to out
//   M = B*T = 262144, N = 128, K = 128.  TM = 64 rows / CTA, 256 threads.
//   smem: Ast[k][64] (transposed input tile, 32KB) + Wst[k][128] (64KB).
//   Each thread: 4x8 register micro-tile, K fully resident -> one tile load.
//   FFMA-pipe bound (~64 FMA/cyc/SM) -> ~270us expected on this shape.
// ======================================================================
extern __shared__ float g_smem[];

__global__ void __launch_bounds__(256, 2) igates_kernel(
    const float* __restrict__ inp,
    const float* __restrict__ W_in,
    const float* __restrict__ b_in,
    const float* __restrict__ b_hh,
    float* __restrict__ out)
{
    float* Ast = g_smem;            // [128][64]
    float* Wst = g_smem + 128 * 64; // [128][128]
    const int tid = threadIdx.x;
    const long m0 = (long)blockIdx.x * 64;

    // Load A tile transposed: Ast[k][r] = inp[(m0+r)*NI + k]
    #pragma unroll
    for (int it = 0; it < 8; it++) {
        int f  = tid + it * 256;        // 0 .. 2047
        int r  = f & 63;
        int k4 = f >> 6;                // 0 .. 31
        float4 v = *(const float4*)(inp + (m0 + r) * NI + (long)k4 * 4);
        Ast[(k4 * 4 + 0) * 64 + r] = v.x;
        Ast[(k4 * 4 + 1) * 64 + r] = v.y;
        Ast[(k4 * 4 + 2) * 64 + r] = v.z;
        Ast[(k4 * 4 + 3) * 64 + r] = v.w;
    }
    // Load W transposed: Wst[k][j] = W_in[j*NI + k]
    #pragma unroll
    for (int it = 0; it < 16; it++) {
        int f  = tid + it * 256;        // 0 .. 4095
        int j  = f & 127;
        int k4 = f >> 7;                // 0 .. 31
        float4 v = *(const float4*)(W_in + (long)j * NI + (long)k4 * 4);
        Wst[(k4 * 4 + 0) * 128 + j] = v.x;
        Wst[(k4 * 4 + 1) * 128 + j] = v.y;
        Wst[(k4 * 4 + 2) * 128 + j] = v.z;
        Wst[(k4 * 4 + 3) * 128 + j] = v.w;
    }
    __syncthreads();

    const int tx = tid & 15;   // col group: cols tx*8 .. tx*8+7
    const int ty = tid >> 4;   // row group: rows ty*4 .. ty*4+3

    float acc[4][8];
    #pragma unroll
    for (int r = 0; r < 4; r++)
        #pragma unroll
        for (int c = 0; c < 8; c++) acc[r][c] = 0.f;

    #pragma unroll 8
    for (int k = 0; k < 128; k++) {
        float4 a  = *(const float4*)(Ast + k * 64 + ty * 4);
        float4 w0 = *(const float4*)(Wst + k * 128 + tx * 8);
        float4 w1 = *(const float4*)(Wst + k * 128 + tx * 8 + 4);
        float av[4] = {a.x, a.y, a.z, a.w};
        float wv[8] = {w0.x, w0.y, w0.z, w0.w, w1.x, w1.y, w1.z, w1.w};
        #pragma unroll
        for (int r = 0; r < 4; r++)
            #pragma unroll
            for (int c = 0; c < 8; c++)
                acc[r][c] = fmaf(av[r], wv[c], acc[r][c]);
    }

    float bias[8];
    #pragma unroll
    for (int c = 0; c < 8; c++)
        bias[c] = b_in[tx * 8 + c] + b_hh[tx * 8 + c];

    #pragma unroll
    for (int r = 0; r < 4; r++) {
        long row = m0 + ty * 4 + r;
        float4 o0, o1;
        o0.x = acc[r][0] + bias[0]; o0.y = acc[r][1] + bias[1];
        o0.z = acc[r][2] + bias[2]; o0.w = acc[r][3] + bias[3];
        o1.x = acc[r][4] + bias[4]; o1.y = acc[r][5] + bias[5];
        o1.z = acc[r][6] + bias[6]; o1.w = acc[r][7] + bias[7];
        *(float4*)(out + row * NH + tx * 8)     = o0;
        *(float4*)(out + row * NH + tx * 8 + 4) = o1;
    }
}

// ======================================================================
// Kernel B: sequential recurrence, one CTA per batch row (128 CTAs x 128 thr)
//   h_new[j] = sigmoid(ig[t][j] + sum_i h[i] * W_hh[j][i])
//   - thread j holds W_hh[j][0..127] in 128 registers (loaded once)
//   - h double-buffered in smem -> one __syncthreads per step
//   - ig prefetched 4 steps deep (>=3 full steps of cover ~ >900 cyc,
//     fully hides 577-cyc DRAM latency; igates is 128MB, L2-miss heavy)
//   - streaming loads/stores (.cg/.cs) for the once-touched global traffic
//   - sigmoid via MUFU-only __expf + __fdividef (no Newton refinement)
// ======================================================================
__global__ void __launch_bounds__(128, 1) rnn_scan_kernel(
    const float* __restrict__ hidden0,
    const float* __restrict__ W_hh,
    float* __restrict__ io)    // [B][T][NH], contains igates on entry
{
    __shared__ float hb[2][NH];
    const int j = threadIdx.x;
    const int b = blockIdx.x;

    // W_hh row j into registers (one-time; L2-resident after wave 1)
    float w[128];
    #pragma unroll
    for (int i = 0; i < 128; i++) w[i] = W_hh[(long)j * NH + i];

    hb[0][j] = hidden0[(long)b * NH + j];

    float* row = io + (long)b * TT * NH + j;

    // 4-deep ig prefetch pipeline
    float ig0 = __ldcg(row);
    float ig1 = __ldcg(row + 1L * NH);
    float ig2 = __ldcg(row + 2L * NH);
    float ig3 = __ldcg(row + 3L * NH);

    __syncthreads();
    int cur = 0;

    for (int t = 0; t < TT; t++) {
        float ig_next = (t + 4 < TT) ? __ldcg(row + (long)(t + 4) * NH) : 0.f;

        float a0 = 0.f, a1 = 0.f, a2 = 0.f, a3 = 0.f;
        const float4* h4 = (const float4*)(&hb[cur][0]);
        #pragma unroll
        for (int i = 0; i < 32; i++) {
            float4 hv = h4[i];   // broadcast LDS.128, conflict-free
            a0 = fmaf(w[4 * i + 0], hv.x, a0);
            a1 = fmaf(w[4 * i + 1], hv.y, a1);
            a2 = fmaf(w[4 * i + 2], hv.z, a2);
            a3 = fmaf(w[4 * i + 3], hv.w, a3);
        }
        float pre = ig0 + ((a0 + a1) + (a2 + a3));
        float h = __fdividef(1.0f, 1.0f + __expf(-pre));

        __stcs(row + (long)t * NH, h);   // overwrite igates slot with output h
        hb[cur ^ 1][j] = h;
        __syncthreads();
        cur ^= 1;

        ig0 = ig1; ig1 = ig2; ig2 = ig3; ig3 = ig_next;
    }
}

// ======================================================================
extern "C" void kernel_launch(void* const* d_in, const int* in_sizes, int n_in,
                              void* d_out, int out_size)
{
    const float* inp     = (const float*)d_in[0];  // [B,T,NI]
    const float* hidden0 = (const float*)d_in[1];  // [B,NH]
    const float* W_in    = (const float*)d_in[2];  // [NH,NI]
    const float* b_in    = (const float*)d_in[3];  // [NH]
    const float* W_hh    = (const float*)d_in[4];  // [NH,NH]
    const float* b_hh    = (const float*)d_in[5];  // [NH]
    float* out = (float*)d_out;                    // [B,T,NH]

    cudaFuncSetAttribute(igates_kernel,
                         cudaFuncAttributeMaxDynamicSharedMemorySize, 98304);

    const int n_tiles = (BB * TT) / 64;   // 4096
    igates_kernel<<<n_tiles, 256, 98304>>>(inp, W_in, b_in, b_hh, out);
    rnn_scan_kernel<<<BB, 128>>>(hidden0, W_hh, out);
}